// round 6
// baseline (speedup 1.0000x reference)
#include <cuda_runtime.h>
#include <math.h>

// Problem constants
#define NB 32     // batch
#define SS 12     // seq len
#define FF 128    // features
#define KH 8      // heads
#define HH 64     // head dim
#define CC 64     // out channels
#define NN 512    // nodes
#define SEGS 4    // n-segments for Wf reduction (512/4 = 128 rows/segment)

#define FEAT_BLOCKS NB                   // 32 feature blocks FIRST (long pole, overlap stream)
#define WF_BLOCKS (CC * SEGS)            // 256 wfsum blocks
#define TOTAL_BLOCKS (FEAT_BLOCKS + WF_BLOCKS)   // 288

// Scratch (no allocations allowed)
__device__ float g_v[NB * CC];              // per-batch feature vector v[b][c]
__device__ float g_wfpart[CC * SEGS * CC];  // partials, layout [c2][seg][c]  (64 KB)
__device__ unsigned int g_done;             // arrival counter (zero-init, self-resetting)

// Shared scratch (union across the three roles)
//  wf:      sred 1024 floats
//  feature: xl 128 + hp 512 + red 256 = 896 floats
//  finale:  sv 2048 + sw 64*68=4352 + sbf 64 = 6464 floats
#define SV_OFF  0
#define SW_OFF  2048
#define SBF_OFF 6400
#define SBUF_FLOATS 6464

__global__ void __launch_bounds__(256, 4) kFused(
    const float* __restrict__ Wf,
    const float* __restrict__ x,
    const float* __restrict__ W_heads,
    const float* __restrict__ W_out,
    const float* __restrict__ bf,
    float* __restrict__ out)
{
    __shared__ __align__(16) float sbuf[SBUF_FLOATS];
    int bid = blockIdx.x;
    int tid = threadIdx.x;

    if (bid >= FEAT_BLOCKS) {
        // ---------------- Wf segment reduction ----------------
        // g_wfpart[c2][seg][c] = sum_{n in seg} Wf[c2][n*64 + c]
        int wb  = bid - FEAT_BLOCKS;
        int c2  = wb >> 2;           // 0..63
        int seg = wb & 3;            // 0..3
        int lane = tid & 15;         // float4 index within 64-float row
        int np   = tid >> 4;         // 16 n-partitions, 8 rows each

        const float4* base = (const float4*)(Wf + (size_t)c2 * (NN * CC));

        int n0 = seg * 128 + np * 8;
        // 8 independent float4 loads (front-batched for MLP)
        float4 v0 = base[(n0 + 0) * 16 + lane];
        float4 v1 = base[(n0 + 1) * 16 + lane];
        float4 v2 = base[(n0 + 2) * 16 + lane];
        float4 v3 = base[(n0 + 3) * 16 + lane];
        float4 v4 = base[(n0 + 4) * 16 + lane];
        float4 v5 = base[(n0 + 5) * 16 + lane];
        float4 v6 = base[(n0 + 6) * 16 + lane];
        float4 v7 = base[(n0 + 7) * 16 + lane];
        float4 acc;
        acc.x = ((v0.x + v1.x) + (v2.x + v3.x)) + ((v4.x + v5.x) + (v6.x + v7.x));
        acc.y = ((v0.y + v1.y) + (v2.y + v3.y)) + ((v4.y + v5.y) + (v6.y + v7.y));
        acc.z = ((v0.z + v1.z) + (v2.z + v3.z)) + ((v4.z + v5.z) + (v6.z + v7.z));
        acc.w = ((v0.w + v1.w) + (v2.w + v3.w)) + ((v4.w + v5.w) + (v6.w + v7.w));

        float4* sred = (float4*)sbuf;
        sred[tid] = acc;
        __syncthreads();
        #pragma unroll
        for (int s = 8; s >= 1; s >>= 1) {
            if (np < s) {
                float4 o = sred[(np + s) * 16 + lane];
                float4 m = sred[np * 16 + lane];
                m.x += o.x; m.y += o.y; m.z += o.z; m.w += o.w;
                sred[np * 16 + lane] = m;
            }
            __syncthreads();
        }
        if (tid < 16) {
            ((float4*)(g_wfpart + ((size_t)c2 * SEGS + seg) * CC))[lane] = sred[lane];
        }
    } else {
        // ---------------- per-batch feature vector ----------------
        // v[b][c] = sum_j elu( x_last[b] . W_heads[:,:,j] ) * W_out[j][c]
        int b = bid;

        float* xl  = sbuf;            // 128
        float* hp  = sbuf + 128;      // 512
        float* red = sbuf + 640;      // 256

        if (tid < FF) xl[tid] = x[b * SS * FF + (SS - 1) * FF + tid];
        __syncthreads();

        #pragma unroll
        for (int rep = 0; rep < 2; ++rep) {
            int j = tid + rep * 256;
            int k = j >> 6;
            int h = j & 63;
            const float* w = W_heads + (k * FF) * HH + h;   // lanes contiguous in h
            float acc = 0.f;
            #pragma unroll 8
            for (int f = 0; f < FF; ++f)
                acc = fmaf(xl[f], w[f * HH], acc);
            hp[j] = (acc > 0.f) ? acc : expm1f(acc);   // elu (alpha=1)
        }
        __syncthreads();

        {
            int c = tid & 63;
            int part = tid >> 6;
            float acc = 0.f;
            int j0 = part * 128;
            #pragma unroll 8
            for (int j = j0; j < j0 + 128; ++j)
                acc = fmaf(hp[j], W_out[j * CC + c], acc);
            red[part * 64 + c] = acc;
        }
        __syncthreads();
        #pragma unroll
        for (int s = 2; s >= 1; s >>= 1) {
            int c = tid & 63;
            int part = tid >> 6;
            if (part < s) red[part * 64 + c] += red[(part + s) * 64 + c];
            __syncthreads();
        }
        if (tid < CC) g_v[b * CC + tid] = red[tid];
    }

    // ---------------- arrive; last block does the finale ----------------
    __shared__ unsigned int s_last;
    __threadfence();                 // release: make this block's writes visible
    __syncthreads();                 // all threads' stores done before arrive
    if (tid == 0) {
        unsigned int old = atomicAdd(&g_done, 1u);
        s_last = (old == TOTAL_BLOCKS - 1) ? 1u : 0u;
        if (s_last) g_done = 0;      // reset for next launch/replay (we are alone)
    }
    __syncthreads();
    if (!s_last) return;
    __threadfence();                 // acquire side

    // ---------------- finale (one block, data L2-resident, ~72 KB) ----------------
    float4* sv4 = (float4*)(sbuf + SV_OFF);     // 512 float4  (v, all batches)
    float4* sw4 = (float4*)(sbuf + SW_OFF);     // 64 rows x 17 float4 (padded)
    float*  sbf = sbuf + SBF_OFF;               // 64

    // g_v -> shared (2 float4 / thread)
    const float4* gv4 = (const float4*)g_v;
    sv4[tid]       = gv4[tid];
    sv4[tid + 256] = gv4[tid + 256];
    if (tid < CC) sbf[tid] = bf[tid];

    // sw[c2][c] = sum_seg g_wfpart[c2][seg][c]   (4 items/thread, 4 loads each)
    const float4* p4 = (const float4*)g_wfpart;
    #pragma unroll
    for (int k = 0; k < 4; ++k) {
        int item = tid + k * 256;     // 1024 items = 64 c2 x 16 lanes
        int c2i  = item >> 4;
        int ln   = item & 15;
        const float4* row = p4 + (size_t)c2i * (SEGS * 16) + ln;
        float4 t0 = row[0 * 16];
        float4 t1 = row[1 * 16];
        float4 t2 = row[2 * 16];
        float4 t3 = row[3 * 16];
        float4 s;
        s.x = (t0.x + t1.x) + (t2.x + t3.x);
        s.y = (t0.y + t1.y) + (t2.y + t3.y);
        s.z = (t0.z + t1.z) + (t2.z + t3.z);
        s.w = (t0.w + t1.w) + (t2.w + t3.w);
        sw4[c2i * 17 + ln] = s;
    }
    __syncthreads();

    // out[b][c2] = bf[c2] + dot(v[b], sw[c2])   (8 outputs/thread)
    {
        int b = tid >> 3;             // 0..31
        const float4* svb = sv4 + b * 16;
        #pragma unroll 2
        for (int k = 0; k < 8; ++k) {
            int c2o = (tid & 7) + k * 8;
            const float4* swr = sw4 + c2o * 17;
            float acc = sbf[c2o];
            #pragma unroll
            for (int j = 0; j < 16; ++j) {
                float4 a = svb[j];
                float4 w = swr[j];
                acc = fmaf(a.x, w.x, acc);
                acc = fmaf(a.y, w.y, acc);
                acc = fmaf(a.z, w.z, acc);
                acc = fmaf(a.w, w.w, acc);
            }
            out[b * CC + c2o] = acc;
        }
    }
}

// ---------------------------------------------------------------------------
// Inputs (metadata order):
//   0: x        (32,12,128)   f32
//   1: W_heads  (8,128,64)    f32
//   2: a1_heads (8,64)        f32   (unused: softmax over identical rows is uniform)
//   3: a2_heads (8,64)        f32   (unused)
//   4: W_out    (512,64)      f32
//   5: a1_out   (64)          f32   (unused)
//   6: a2_out   (64)          f32   (unused)
//   7: Wf       (64,32768)    f32
//   8: bf       (64)          f32
// Output: (32,64) f32
// ---------------------------------------------------------------------------
extern "C" void kernel_launch(void* const* d_in, const int* in_sizes, int n_in,
                              void* d_out, int out_size)
{
    const float* x       = (const float*)d_in[0];
    const float* W_heads = (const float*)d_in[1];
    const float* W_out   = (const float*)d_in[4];
    const float* Wf      = (const float*)d_in[7];
    const float* bf      = (const float*)d_in[8];
    float* out = (float*)d_out;

    kFused<<<TOTAL_BLOCKS, 256>>>(Wf, x, W_heads, W_out, bf, out);
}

// round 7
// speedup vs baseline: 1.4513x; 1.4513x over previous
#include <cuda_runtime.h>
#include <math.h>

// Problem constants
#define NB 32     // batch
#define SS 12     // seq len
#define FF 128    // features
#define KH 8      // heads
#define HH 64     // head dim
#define CC 64     // out channels
#define NN 512    // nodes
#define SEGS 16   // n-segments for Wf reduction (512/16 = 32 rows/segment)

#define FEAT_BLOCKS NB                    // 32 feature blocks FIRST (overlap with stream)
#define WF_BLOCKS (CC * SEGS)             // 1024 stream blocks
#define TOTAL_BLOCKS (FEAT_BLOCKS + WF_BLOCKS)

// Scratch (no allocations allowed)
__device__ float g_v[NB * CC];              // per-batch feature vector v[b][c]
__device__ float g_wfpart[CC * SEGS * CC];  // partials, layout [c2][seg][c]

// ---------------------------------------------------------------------------
// Kernel A (block-specialized):
//   blocks [0, 32):      per-batch features (latency-optimized, f-parallel)
//   blocks [32, 32+1024): g_wfpart[c2][seg][c] = sum_{n in seg} Wf[c2][n*64+c]
// 256 threads/block.
// ---------------------------------------------------------------------------
__global__ void __launch_bounds__(256) kA_fused(
    const float* __restrict__ Wf,
    const float* __restrict__ x,
    const float* __restrict__ W_heads,
    const float* __restrict__ W_out)
{
    __shared__ __align__(16) float sbuf[128 + 2048 + 512 + 256];
    int bid = blockIdx.x;
    int tid = threadIdx.x;

    if (bid >= FEAT_BLOCKS) {
        // ---------------- Wf segment reduction (as R3, measured) ----------------
        int wb  = bid - FEAT_BLOCKS;
        int c2  = wb >> 4;           // 0..63
        int seg = wb & 15;           // 0..15
        int lane = tid & 15;         // float4 index within 64-float row
        int np   = tid >> 4;         // 16 n-partitions, 2 rows each

        const float4* base = (const float4*)(Wf + (size_t)c2 * (NN * CC));

        float4 acc;
        {
            int n0 = seg * 32 + np * 2;
            float4 v0 = base[(n0 + 0) * 16 + lane];
            float4 v1 = base[(n0 + 1) * 16 + lane];
            acc.x = v0.x + v1.x; acc.y = v0.y + v1.y;
            acc.z = v0.z + v1.z; acc.w = v0.w + v1.w;
        }

        float4* sred = (float4*)sbuf;
        sred[tid] = acc;
        __syncthreads();
        #pragma unroll
        for (int s = 8; s >= 1; s >>= 1) {
            if (np < s) {
                float4 o = sred[(np + s) * 16 + lane];
                float4 m = sred[np * 16 + lane];
                m.x += o.x; m.y += o.y; m.z += o.z; m.w += o.w;
                sred[np * 16 + lane] = m;
            }
            __syncthreads();
        }
        if (tid < 16) {
            ((float4*)(g_wfpart + ((size_t)c2 * SEGS + seg) * CC))[lane] = sred[lane];
        }
    } else {
        // ---------------- per-batch feature vector (latency-optimized) ----------
        // v[b][c] = sum_j elu( x_last[b] . W_heads[:,:,j] ) * W_out[j][c]
        int b = bid;

        float* xl    = sbuf;                 // 128
        float* hpart = sbuf + 128;           // [4 fparts][512 j]
        float* hp    = sbuf + 128 + 2048;    // 512
        float* red   = sbuf + 128 + 2048 + 512; // 256

        if (tid < 32)
            ((float4*)xl)[tid] = ((const float4*)(x + b * SS * FF + (SS - 1) * FF))[tid];
        __syncthreads();

        // hp partials: 512 slots = 4 f-partitions x 128 j-quads, 2 slots/thread.
        // Each slot: dot of 32 f's for 4 consecutive j's (float4 along h).
        #pragma unroll
        for (int s = 0; s < 2; ++s) {
            int slot  = tid + s * 256;       // 0..511
            int fpart = slot >> 7;           // 0..3
            int jq    = slot & 127;          // j-quad, j0 = jq*4
            int k     = jq >> 4;             // head index
            int h0    = (jq & 15) * 4;
            const float4* w = (const float4*)(W_heads + (size_t)k * FF * HH + h0);
            int f0 = fpart * 32;
            float4 acc = make_float4(0.f, 0.f, 0.f, 0.f);
            #pragma unroll 8
            for (int i = 0; i < 32; ++i) {
                float4 wv = w[(f0 + i) * 16];    // 64 floats per f-row = 16 float4
                float xv = xl[f0 + i];           // warp-broadcast
                acc.x = fmaf(xv, wv.x, acc.x);
                acc.y = fmaf(xv, wv.y, acc.y);
                acc.z = fmaf(xv, wv.z, acc.z);
                acc.w = fmaf(xv, wv.w, acc.w);
            }
            ((float4*)hpart)[fpart * 128 + jq] = acc;
        }
        __syncthreads();

        // reduce f-partitions + elu
        #pragma unroll
        for (int s = 0; s < 2; ++s) {
            int j = tid + s * 256;
            float sum = (hpart[j] + hpart[512 + j]) + (hpart[1024 + j] + hpart[1536 + j]);
            hp[j] = (sum > 0.f) ? sum : expm1f(sum);   // elu (alpha=1)
        }
        __syncthreads();

        // v[c] = sum_j hp[j]*W_out[j][c]; 4 j-parts, 2 independent chains each
        {
            int c = tid & 63;
            int part = tid >> 6;
            int j0 = part * 128;
            float acc0 = 0.f, acc1 = 0.f;
            #pragma unroll 16
            for (int j = 0; j < 64; ++j) {
                acc0 = fmaf(hp[j0 + j],      W_out[(j0 + j) * CC + c],      acc0);
                acc1 = fmaf(hp[j0 + 64 + j], W_out[(j0 + 64 + j) * CC + c], acc1);
            }
            red[part * 64 + c] = acc0 + acc1;
        }
        __syncthreads();
        #pragma unroll
        for (int s = 2; s >= 1; s >>= 1) {
            int c = tid & 63;
            int part = tid >> 6;
            if (part < s) red[part * 64 + c] += red[(part + s) * 64 + c];
            __syncthreads();
        }
        if (tid < CC) g_v[b * CC + tid] = red[tid];
    }
}

// ---------------------------------------------------------------------------
// Kernel B: final output. Grid = 64 blocks (c2), 128 threads. (As R3, measured.)
// ---------------------------------------------------------------------------
__global__ void __launch_bounds__(128) kB_final(
    const float* __restrict__ bf,
    float* __restrict__ out)
{
    int c2 = blockIdx.x;
    int tid = threadIdx.x;

    __shared__ float4 tmp[SEGS * 16];    // [seg][lane4] partials for this c2
    __shared__ float  sv[NB * CC];       // all v
    __shared__ float  sw[CC];

    // Issue all global loads (independent, pipelined)
    const float4* pp = (const float4*)(g_wfpart + (size_t)c2 * SEGS * CC);
    float4 p0 = pp[tid];
    float4 p1 = pp[tid + 128];

    const float4* vp = (const float4*)g_v;
    float4 v0 = vp[tid];
    float4 v1 = vp[tid + 128];
    float4 v2 = vp[tid + 256];
    float4 v3 = vp[tid + 384];

    float bias = bf[c2];

    tmp[tid] = p0;
    tmp[tid + 128] = p1;
    ((float4*)sv)[tid]       = v0;
    ((float4*)sv)[tid + 128] = v1;
    ((float4*)sv)[tid + 256] = v2;
    ((float4*)sv)[tid + 384] = v3;
    __syncthreads();

    // sw[c] = sum over 16 segs
    if (tid < CC) {
        const float* t = (const float*)tmp;
        float w = 0.f;
        #pragma unroll
        for (int s = 0; s < SEGS; ++s)
            w += t[s * CC + tid];
        sw[tid] = w;
    }
    __syncthreads();

    // out[b][c2]: tid -> b = tid/4, part = tid%4 (16 c's each), shuffle-reduce
    {
        int b = tid >> 2;
        int part = tid & 3;
        const float* svb = sv + b * CC + part * 16;
        const float* swp = sw + part * 16;
        float acc = 0.f;
        #pragma unroll
        for (int c = 0; c < 16; ++c)
            acc = fmaf(svb[c], swp[c], acc);
        acc += __shfl_xor_sync(0xffffffffu, acc, 1);
        acc += __shfl_xor_sync(0xffffffffu, acc, 2);
        if (part == 0)
            out[b * CC + c2] = acc + bias;
    }
}

// ---------------------------------------------------------------------------
// Inputs (metadata order):
//   0: x        (32,12,128)   f32
//   1: W_heads  (8,128,64)    f32
//   2: a1_heads (8,64)        f32   (unused: softmax over identical rows is uniform)
//   3: a2_heads (8,64)        f32   (unused)
//   4: W_out    (512,64)      f32
//   5: a1_out   (64)          f32   (unused)
//   6: a2_out   (64)          f32   (unused)
//   7: Wf       (64,32768)    f32
//   8: bf       (64)          f32
// Output: (32,64) f32
// ---------------------------------------------------------------------------
extern "C" void kernel_launch(void* const* d_in, const int* in_sizes, int n_in,
                              void* d_out, int out_size)
{
    const float* x       = (const float*)d_in[0];
    const float* W_heads = (const float*)d_in[1];
    const float* W_out   = (const float*)d_in[4];
    const float* Wf      = (const float*)d_in[7];
    const float* bf      = (const float*)d_in[8];
    float* out = (float*)d_out;

    kA_fused<<<TOTAL_BLOCKS, 256>>>(Wf, x, W_heads, W_out);
    kB_final<<<CC, 128>>>(bf, out);
}